// round 2
// baseline (speedup 1.0000x reference)
#include <cuda_runtime.h>
#include <math.h>

// 256 threads/CTA, each CTA processes ROWS_PER_CTA consecutive rows of 1024
// floats. w,b live in registers for the whole CTA. Row r+1's X load is
// prefetched before row r's scan/scatter/epilogue (software pipeline).
// Per row: warp-shuffle scan -> warp totals in smem -> one sync ->
// every thread redundantly reduces the 8 totals (broadcast LDS) ->
// stable scatter of finite values to smem -> one sync -> float4 affine
// epilogue with zero-padded tail.

#define SIZE 1024
#define THREADS 256
#define ROWS_PER_CTA 16

__global__ __launch_bounds__(THREADS)
void nan_dense_kernel(const float4* __restrict__ X4,
                      const float* __restrict__ w,
                      const float* __restrict__ b,
                      float4* __restrict__ out4,
                      int batch)
{
    __shared__ float s[SIZE];
    __shared__ int wtot[8];

    const int t    = threadIdx.x;
    const int lane = t & 31;
    const int wid  = t >> 5;

    // Per-CTA constants in registers (amortized over ROWS_PER_CTA rows).
    const float4 wv = reinterpret_cast<const float4*>(w)[t];
    const float4 bv = reinterpret_cast<const float4*>(b)[t];

    const long long row0 = (long long)blockIdx.x * ROWS_PER_CTA;
    const int nrows = (batch - row0 < ROWS_PER_CTA) ? (int)(batch - row0)
                                                    : ROWS_PER_CTA;
    const int V = SIZE / 4;   // 256 float4 per row

    // Prefetch first row.
    float4 xv = X4[row0 * V + t];

    for (int r = 0; r < nrows; ++r) {
        const float4 cur = xv;
        if (r + 1 < nrows)
            xv = X4[(row0 + r + 1) * V + t];   // prefetch next row

        float v[4] = {cur.x, cur.y, cur.z, cur.w};
        bool fin[4];
        int cnt = 0;
#pragma unroll
        for (int k = 0; k < 4; ++k) {
            fin[k] = isfinite(v[k]);
            cnt += fin[k] ? 1 : 0;
        }

        // Warp-level inclusive scan of per-thread finite counts.
        int incl = cnt;
#pragma unroll
        for (int d = 1; d < 32; d <<= 1) {
            int n = __shfl_up_sync(0xffffffffu, incl, d);
            if (lane >= d) incl += n;
        }
        if (lane == 31) wtot[wid] = incl;
        __syncthreads();                       // wtot visible to all

        // Every thread redundantly reduces the 8 warp totals (broadcast LDS,
        // conflict-free) -> its warp's exclusive offset + block total.
        int off = 0, total = 0;
#pragma unroll
        for (int i = 0; i < 8; ++i) {
            const int ti = wtot[i];
            total += ti;
            if (i < wid) off += ti;
        }

        // Stable scatter of finite values into the compaction buffer.
        int pos = off + (incl - cnt);
#pragma unroll
        for (int k = 0; k < 4; ++k) {
            if (fin[k]) s[pos++] = v[k];
        }
        __syncthreads();                       // scatter complete

        // Vectorized affine epilogue with zero-padded tail.
        const float4 sv = reinterpret_cast<const float4*>(s)[t];
        const int base = t << 2;
        float4 o;
        o.x = (base + 0 < total) ? fmaf(sv.x, wv.x, bv.x) : 0.0f;
        o.y = (base + 1 < total) ? fmaf(sv.y, wv.y, bv.y) : 0.0f;
        o.z = (base + 2 < total) ? fmaf(sv.z, wv.z, bv.z) : 0.0f;
        o.w = (base + 3 < total) ? fmaf(sv.w, wv.w, bv.w) : 0.0f;

        out4[(row0 + r) * V + t] = o;
        // No extra barrier needed: iter i's reads of s/wtot all precede the
        // next iteration's first __syncthreads, which precedes its writers.
    }
}

extern "C" void kernel_launch(void* const* d_in, const int* in_sizes, int n_in,
                              void* d_out, int out_size)
{
    const float* X = (const float*)d_in[0];
    const float* w = (const float*)d_in[1];
    const float* b = (const float*)d_in[2];
    float* out = (float*)d_out;

    const int batch = in_sizes[0] / SIZE;                  // 131072
    const int grid  = (batch + ROWS_PER_CTA - 1) / ROWS_PER_CTA;
    nan_dense_kernel<<<grid, THREADS>>>(
        reinterpret_cast<const float4*>(X), w, b,
        reinterpret_cast<float4*>(out), batch);
}

// round 3
// speedup vs baseline: 1.0858x; 1.0858x over previous
#include <cuda_runtime.h>
#include <math.h>

// 256 threads/CTA, ROWS_PER_CTA=4 rows per CTA (w,b register-resident,
// moderate reg pressure -> high occupancy). Streaming cache hints:
// __ldcs on X (no reuse), __stcs on out (no reuse) keep L2 ways free and
// improve DRAM write-combining. One barrier per phase; warp totals reduced
// redundantly per thread (broadcast LDS).

#define SIZE 1024
#define THREADS 256
#define ROWS_PER_CTA 4

__global__ __launch_bounds__(THREADS)
void nan_dense_kernel(const float4* __restrict__ X4,
                      const float* __restrict__ w,
                      const float* __restrict__ b,
                      float4* __restrict__ out4)
{
    __shared__ float s[SIZE];
    __shared__ int wtot[8];

    const int t    = threadIdx.x;
    const int lane = t & 31;
    const int wid  = t >> 5;

    const float4 wv = reinterpret_cast<const float4*>(w)[t];
    const float4 bv = reinterpret_cast<const float4*>(b)[t];

    const long long row0 = (long long)blockIdx.x * ROWS_PER_CTA;
    const int V = SIZE / 4;   // 256 float4 per row

    // Prefetch first row (streaming: evict-first).
    float4 xv = __ldcs(&X4[row0 * V + t]);

#pragma unroll
    for (int r = 0; r < ROWS_PER_CTA; ++r) {
        const float4 cur = xv;
        if (r + 1 < ROWS_PER_CTA)
            xv = __ldcs(&X4[(row0 + r + 1) * V + t]);   // prefetch next row

        float v[4] = {cur.x, cur.y, cur.z, cur.w};
        bool fin[4];
        int cnt = 0;
#pragma unroll
        for (int k = 0; k < 4; ++k) {
            fin[k] = isfinite(v[k]);
            cnt += fin[k] ? 1 : 0;
        }

        // Warp-level inclusive scan of per-thread finite counts.
        int incl = cnt;
#pragma unroll
        for (int d = 1; d < 32; d <<= 1) {
            int n = __shfl_up_sync(0xffffffffu, incl, d);
            if (lane >= d) incl += n;
        }
        if (lane == 31) wtot[wid] = incl;
        __syncthreads();                       // wtot visible

        // Redundant reduce of the 8 warp totals (broadcast LDS).
        int off = 0, total = 0;
#pragma unroll
        for (int i = 0; i < 8; ++i) {
            const int ti = wtot[i];
            total += ti;
            if (i < wid) off += ti;
        }

        // Stable scatter of finite values.
        int pos = off + (incl - cnt);
#pragma unroll
        for (int k = 0; k < 4; ++k) {
            if (fin[k]) s[pos++] = v[k];
        }
        __syncthreads();                       // scatter complete

        const float4 sv = reinterpret_cast<const float4*>(s)[t];
        const int base = t << 2;
        float4 o;
        o.x = (base + 0 < total) ? fmaf(sv.x, wv.x, bv.x) : 0.0f;
        o.y = (base + 1 < total) ? fmaf(sv.y, wv.y, bv.y) : 0.0f;
        o.z = (base + 2 < total) ? fmaf(sv.z, wv.z, bv.z) : 0.0f;
        o.w = (base + 3 < total) ? fmaf(sv.w, wv.w, bv.w) : 0.0f;

        __stcs(&out4[(row0 + r) * V + t], o);  // streaming store
        // Next iteration's first __syncthreads orders s/wtot reuse.
    }
}

extern "C" void kernel_launch(void* const* d_in, const int* in_sizes, int n_in,
                              void* d_out, int out_size)
{
    const float* X = (const float*)d_in[0];
    const float* w = (const float*)d_in[1];
    const float* b = (const float*)d_in[2];
    float* out = (float*)d_out;

    const int batch = in_sizes[0] / SIZE;                  // 131072 (mult of 4)
    const int grid  = batch / ROWS_PER_CTA;
    nan_dense_kernel<<<grid, THREADS>>>(
        reinterpret_cast<const float4*>(X), w, b,
        reinterpret_cast<float4*>(out));
}

// round 4
// speedup vs baseline: 1.1231x; 1.0344x over previous
#include <cuda_runtime.h>
#include <math.h>

// One CTA (256 threads) per row of 1024 floats. Lean register budget
// (__launch_bounds__(256, 8) -> <=32 regs -> 8 CTAs/SM, occ ~90%).
// w,b fetched per row via __ldg (broadcast, L1/L2-hot); X read with __ldcs
// and out written with __stcs (streaming, evict-first, no L2 pollution).
// Two barriers per row: scan totals, then scatter completion.

#define SIZE 1024
#define THREADS 256

__global__ __launch_bounds__(THREADS, 8)
void nan_dense_kernel(const float4* __restrict__ X4,
                      const float4* __restrict__ w4,
                      const float4* __restrict__ b4,
                      float4* __restrict__ out4)
{
    __shared__ float s[SIZE];
    __shared__ int wtot[8];

    const int row  = blockIdx.x;
    const int t    = threadIdx.x;
    const int lane = t & 31;
    const int wid  = t >> 5;
    const int V = SIZE / 4;   // 256 float4 per row

    const float4 cur = __ldcs(&X4[(long long)row * V + t]);

    float v[4] = {cur.x, cur.y, cur.z, cur.w};
    bool fin[4];
    int cnt = 0;
#pragma unroll
    for (int k = 0; k < 4; ++k) {
        fin[k] = isfinite(v[k]);
        cnt += fin[k] ? 1 : 0;
    }

    // Warp-level inclusive scan of per-thread finite counts.
    int incl = cnt;
#pragma unroll
    for (int d = 1; d < 32; d <<= 1) {
        int n = __shfl_up_sync(0xffffffffu, incl, d);
        if (lane >= d) incl += n;
    }
    if (lane == 31) wtot[wid] = incl;
    __syncthreads();                       // warp totals visible

    // Redundant per-thread reduce of 8 warp totals (broadcast LDS).
    int off = 0, total = 0;
#pragma unroll
    for (int i = 0; i < 8; ++i) {
        const int ti = wtot[i];
        total += ti;
        if (i < wid) off += ti;
    }

    // Stable scatter of finite values into compaction buffer.
    int pos = off + (incl - cnt);
#pragma unroll
    for (int k = 0; k < 4; ++k) {
        if (fin[k]) s[pos++] = v[k];
    }
    __syncthreads();                       // scatter complete

    // Affine epilogue; w,b loaded here (L1/L2-hot after first wave).
    const float4 wv = __ldg(&w4[t]);
    const float4 bv = __ldg(&b4[t]);
    const float4 sv = reinterpret_cast<const float4*>(s)[t];

    const int base = t << 2;
    float4 o;
    o.x = (base + 0 < total) ? fmaf(sv.x, wv.x, bv.x) : 0.0f;
    o.y = (base + 1 < total) ? fmaf(sv.y, wv.y, bv.y) : 0.0f;
    o.z = (base + 2 < total) ? fmaf(sv.z, wv.z, bv.z) : 0.0f;
    o.w = (base + 3 < total) ? fmaf(sv.w, wv.w, bv.w) : 0.0f;

    __stcs(&out4[(long long)row * V + t], o);
}

extern "C" void kernel_launch(void* const* d_in, const int* in_sizes, int n_in,
                              void* d_out, int out_size)
{
    const float* X = (const float*)d_in[0];
    const float* w = (const float*)d_in[1];
    const float* b = (const float*)d_in[2];
    float* out = (float*)d_out;

    const int batch = in_sizes[0] / SIZE;   // 131072
    nan_dense_kernel<<<batch, THREADS>>>(
        reinterpret_cast<const float4*>(X),
        reinterpret_cast<const float4*>(w),
        reinterpret_cast<const float4*>(b),
        reinterpret_cast<float4*>(out));
}

// round 5
// speedup vs baseline: 1.1833x; 1.0536x over previous
#include <cuda_runtime.h>
#include <math.h>

// 256 threads/CTA, 2 rows per CTA, fused pipeline:
//   load both rows (MLP=2) -> ballot-based stable compaction positions
//   (no shuffles, no scan chain) -> one barrier -> both scatters ->
//   one barrier -> register-resident w/b affine epilogue, streaming stores.
// Ordering within a warp is (thread, k) = element-major, matching the
// original index 4t+k, so popc-prefix over per-element ballots is a
// stable compaction.

#define SIZE 1024
#define THREADS 256

__global__ __launch_bounds__(THREADS, 5)
void nan_dense_kernel(const float4* __restrict__ X4,
                      const float4* __restrict__ w4,
                      const float4* __restrict__ b4,
                      float4* __restrict__ out4)
{
    __shared__ float s0[SIZE];
    __shared__ float s1[SIZE];
    __shared__ int wtot[2][8];

    const int t    = threadIdx.x;
    const int lane = t & 31;
    const int wid  = t >> 5;
    const int V    = SIZE / 4;                  // 256 float4 per row

    const long long r0 = (long long)blockIdx.x * 2;

    // Both rows' loads issued back-to-back (MLP=2), streaming.
    const float4 a = __ldcs(&X4[r0 * V + t]);
    const float4 c = __ldcs(&X4[(r0 + 1) * V + t]);
    const float4 wv = __ldg(&w4[t]);
    const float4 bv = __ldg(&b4[t]);

    float va[4] = {a.x, a.y, a.z, a.w};
    float vb[4] = {c.x, c.y, c.z, c.w};
    bool fa[4], fb[4];
    unsigned mA[4], mB[4];
#pragma unroll
    for (int k = 0; k < 4; ++k) {
        fa[k] = isfinite(va[k]);
        fb[k] = isfinite(vb[k]);
        mA[k] = __ballot_sync(0xffffffffu, fa[k]);
        mB[k] = __ballot_sync(0xffffffffu, fb[k]);
    }

    // Warp totals are lane-uniform from the ballots.
    if (lane == 0) {
        wtot[0][wid] = __popc(mA[0]) + __popc(mA[1]) + __popc(mA[2]) + __popc(mA[3]);
        wtot[1][wid] = __popc(mB[0]) + __popc(mB[1]) + __popc(mB[2]) + __popc(mB[3]);
    }
    __syncthreads();

    // Redundant per-thread reduce of warp totals (broadcast LDS, conflict-free).
    int offA = 0, totA = 0, offB = 0, totB = 0;
#pragma unroll
    for (int i = 0; i < 8; ++i) {
        const int tA = wtot[0][i];
        const int tB = wtot[1][i];
        totA += tA; totB += tB;
        if (i < wid) { offA += tA; offB += tB; }
    }

    // Stable positions: warp offset + finite-count among lower lanes (all k)
    // + finite-count among this thread's lower k.
    const unsigned lt = (1u << lane) - 1u;
    int posA = offA + __popc(mA[0] & lt) + __popc(mA[1] & lt)
                    + __popc(mA[2] & lt) + __popc(mA[3] & lt);
    int posB = offB + __popc(mB[0] & lt) + __popc(mB[1] & lt)
                    + __popc(mB[2] & lt) + __popc(mB[3] & lt);
#pragma unroll
    for (int k = 0; k < 4; ++k) {
        if (fa[k]) s0[posA++] = va[k];
        if (fb[k]) s1[posB++] = vb[k];
    }
    __syncthreads();

    const float4 sa = reinterpret_cast<const float4*>(s0)[t];
    const float4 sb = reinterpret_cast<const float4*>(s1)[t];
    const int base = t << 2;

    float4 oa, ob;
    oa.x = (base + 0 < totA) ? fmaf(sa.x, wv.x, bv.x) : 0.0f;
    oa.y = (base + 1 < totA) ? fmaf(sa.y, wv.y, bv.y) : 0.0f;
    oa.z = (base + 2 < totA) ? fmaf(sa.z, wv.z, bv.z) : 0.0f;
    oa.w = (base + 3 < totA) ? fmaf(sa.w, wv.w, bv.w) : 0.0f;
    ob.x = (base + 0 < totB) ? fmaf(sb.x, wv.x, bv.x) : 0.0f;
    ob.y = (base + 1 < totB) ? fmaf(sb.y, wv.y, bv.y) : 0.0f;
    ob.z = (base + 2 < totB) ? fmaf(sb.z, wv.z, bv.z) : 0.0f;
    ob.w = (base + 3 < totB) ? fmaf(sb.w, wv.w, bv.w) : 0.0f;

    __stcs(&out4[r0 * V + t], oa);
    __stcs(&out4[(r0 + 1) * V + t], ob);
}

extern "C" void kernel_launch(void* const* d_in, const int* in_sizes, int n_in,
                              void* d_out, int out_size)
{
    const float* X = (const float*)d_in[0];
    const float* w = (const float*)d_in[1];
    const float* b = (const float*)d_in[2];
    float* out = (float*)d_out;

    const int batch = in_sizes[0] / SIZE;   // 131072 (even)
    nan_dense_kernel<<<batch / 2, THREADS>>>(
        reinterpret_cast<const float4*>(X),
        reinterpret_cast<const float4*>(w),
        reinterpret_cast<const float4*>(b),
        reinterpret_cast<float4*>(out));
}

// round 6
// speedup vs baseline: 1.2409x; 1.0487x over previous
#include <cuda_runtime.h>
#include <math.h>

// 256 threads/CTA, 2 rows per CTA. Ballot-based stable compaction with
// MINIMAL live state across the barrier: only the 8 row values + 2 scalar
// warp-prefix counts survive; finite flags are recomputed at scatter time
// and ballot masks die before the barrier. w,b are loaded in the epilogue
// (L1-hot broadcast). Streaming __ldcs/__stcs on X/out. Two barriers total
// for both rows.

#define SIZE 1024
#define THREADS 256

__global__ __launch_bounds__(THREADS, 6)
void nan_dense_kernel(const float4* __restrict__ X4,
                      const float4* __restrict__ w4,
                      const float4* __restrict__ b4,
                      float4* __restrict__ out4)
{
    __shared__ float s0[SIZE];
    __shared__ float s1[SIZE];
    __shared__ int wtot[2][8];

    const int t    = threadIdx.x;
    const int lane = t & 31;
    const int wid  = t >> 5;
    const int V    = SIZE / 4;                  // 256 float4 per row

    const long long r0 = (long long)blockIdx.x * 2;

    // Two independent row loads in flight (MLP=2), streaming.
    const float4 a = __ldcs(&X4[r0 * V + t]);
    const float4 c = __ldcs(&X4[(r0 + 1) * V + t]);

    float va[4] = {a.x, a.y, a.z, a.w};
    float vb[4] = {c.x, c.y, c.z, c.w};

    // Ballots -> warp totals + per-thread prefix; masks die here.
    const unsigned lt = (1u << lane) - 1u;
    int preA = 0, preB = 0, wtA = 0, wtB = 0;
#pragma unroll
    for (int k = 0; k < 4; ++k) {
        const unsigned mA = __ballot_sync(0xffffffffu, isfinite(va[k]));
        const unsigned mB = __ballot_sync(0xffffffffu, isfinite(vb[k]));
        preA += __popc(mA & lt);  wtA += __popc(mA);
        preB += __popc(mB & lt);  wtB += __popc(mB);
    }
    if (lane == 0) { wtot[0][wid] = wtA; wtot[1][wid] = wtB; }
    __syncthreads();

    // Redundant per-thread reduce of warp totals (broadcast LDS).
    int offA = 0, totA = 0, offB = 0, totB = 0;
#pragma unroll
    for (int i = 0; i < 8; ++i) {
        const int tA = wtot[0][i];
        const int tB = wtot[1][i];
        totA += tA; totB += tB;
        if (i < wid) { offA += tA; offB += tB; }
    }

    // Stable scatter; finite flags recomputed (cheap FSETP).
    int posA = offA + preA;
    int posB = offB + preB;
#pragma unroll
    for (int k = 0; k < 4; ++k) {
        if (isfinite(va[k])) s0[posA++] = va[k];
        if (isfinite(vb[k])) s1[posB++] = vb[k];
    }
    __syncthreads();

    // Epilogue: w/b broadcast loads (L1-hot), affine + zero tail.
    const float4 wv = __ldg(&w4[t]);
    const float4 bv = __ldg(&b4[t]);
    const float4 sa = reinterpret_cast<const float4*>(s0)[t];
    const float4 sb = reinterpret_cast<const float4*>(s1)[t];
    const int base = t << 2;

    float4 oa, ob;
    oa.x = (base + 0 < totA) ? fmaf(sa.x, wv.x, bv.x) : 0.0f;
    oa.y = (base + 1 < totA) ? fmaf(sa.y, wv.y, bv.y) : 0.0f;
    oa.z = (base + 2 < totA) ? fmaf(sa.z, wv.z, bv.z) : 0.0f;
    oa.w = (base + 3 < totA) ? fmaf(sa.w, wv.w, bv.w) : 0.0f;
    ob.x = (base + 0 < totB) ? fmaf(sb.x, wv.x, bv.x) : 0.0f;
    ob.y = (base + 1 < totB) ? fmaf(sb.y, wv.y, bv.y) : 0.0f;
    ob.z = (base + 2 < totB) ? fmaf(sb.z, wv.z, bv.z) : 0.0f;
    ob.w = (base + 3 < totB) ? fmaf(sb.w, wv.w, bv.w) : 0.0f;

    __stcs(&out4[r0 * V + t], oa);
    __stcs(&out4[(r0 + 1) * V + t], ob);
}

extern "C" void kernel_launch(void* const* d_in, const int* in_sizes, int n_in,
                              void* d_out, int out_size)
{
    const float* X = (const float*)d_in[0];
    const float* w = (const float*)d_in[1];
    const float* b = (const float*)d_in[2];
    float* out = (float*)d_out;

    const int batch = in_sizes[0] / SIZE;   // 131072 (even)
    nan_dense_kernel<<<batch / 2, THREADS>>>(
        reinterpret_cast<const float4*>(X),
        reinterpret_cast<const float4*>(w),
        reinterpret_cast<const float4*>(b),
        reinterpret_cast<float4*>(out));
}

// round 7
// speedup vs baseline: 1.2747x; 1.0272x over previous
#include <cuda_runtime.h>
#include <math.h>

// 256 threads/CTA, 4 rows per CTA (MLP=4 per warp), minimal live state
// across the single scan barrier: 16 row floats + 4 prefix ints. Warp
// totals for row pairs are packed as 16-bit halves of one 32-bit word
// (row sums <= 1024 never carry across the halfword), halving the LDS/adds
// in the cross-warp reduce. Finite flags recomputed at scatter. w,b loaded
// in the epilogue (L1-hot broadcast). Streaming __ldcs/__stcs on X/out.
// Two barriers for all four rows.

#define SIZE 1024
#define THREADS 256
#define ROWS 4

__global__ __launch_bounds__(THREADS, 4)
void nan_dense_kernel(const float4* __restrict__ X4,
                      const float4* __restrict__ w4,
                      const float4* __restrict__ b4,
                      float4* __restrict__ out4)
{
    __shared__ float s[ROWS][SIZE];           // 16 KB compaction buffers
    __shared__ unsigned wtAB[8], wtCD[8];     // packed warp totals

    const int t    = threadIdx.x;
    const int lane = t & 31;
    const int wid  = t >> 5;
    const int V    = SIZE / 4;                // 256 float4 per row

    const long long r0 = (long long)blockIdx.x * ROWS;

    // Four independent streaming loads in flight (MLP=4).
    const float4 a0 = __ldcs(&X4[(r0 + 0) * V + t]);
    const float4 a1 = __ldcs(&X4[(r0 + 1) * V + t]);
    const float4 a2 = __ldcs(&X4[(r0 + 2) * V + t]);
    const float4 a3 = __ldcs(&X4[(r0 + 3) * V + t]);

    float v0[4] = {a0.x, a0.y, a0.z, a0.w};
    float v1[4] = {a1.x, a1.y, a1.z, a1.w};
    float v2[4] = {a2.x, a2.y, a2.z, a2.w};
    float v3[4] = {a3.x, a3.y, a3.z, a3.w};

    // Ballots -> per-thread prefix + warp totals; masks die before barrier.
    const unsigned lt = (1u << lane) - 1u;
    int pre0 = 0, pre1 = 0, pre2 = 0, pre3 = 0;
    int w0 = 0, w1 = 0, w2 = 0, w3 = 0;
#pragma unroll
    for (int k = 0; k < 4; ++k) {
        const unsigned m0 = __ballot_sync(0xffffffffu, isfinite(v0[k]));
        const unsigned m1 = __ballot_sync(0xffffffffu, isfinite(v1[k]));
        const unsigned m2 = __ballot_sync(0xffffffffu, isfinite(v2[k]));
        const unsigned m3 = __ballot_sync(0xffffffffu, isfinite(v3[k]));
        pre0 += __popc(m0 & lt);  w0 += __popc(m0);
        pre1 += __popc(m1 & lt);  w1 += __popc(m1);
        pre2 += __popc(m2 & lt);  w2 += __popc(m2);
        pre3 += __popc(m3 & lt);  w3 += __popc(m3);
    }
    if (lane == 0) {
        wtAB[wid] = (unsigned)w0 | ((unsigned)w1 << 16);
        wtCD[wid] = (unsigned)w2 | ((unsigned)w3 << 16);
    }
    __syncthreads();

    // Packed redundant reduce: sums per 16-bit half never exceed 1024.
    unsigned sAB = 0, sCD = 0, oAB = 0, oCD = 0;
#pragma unroll
    for (int i = 0; i < 8; ++i) {
        const unsigned pAB = wtAB[i];
        const unsigned pCD = wtCD[i];
        sAB += pAB; sCD += pCD;
        if (i < wid) { oAB += pAB; oCD += pCD; }
    }
    const int tot0 = sAB & 0xffffu, tot1 = sAB >> 16;
    const int tot2 = sCD & 0xffffu, tot3 = sCD >> 16;

    // Stable scatter; finite flags recomputed (FSETP is cheap).
    int p0 = (int)(oAB & 0xffffu) + pre0;
    int p1 = (int)(oAB >> 16)     + pre1;
    int p2 = (int)(oCD & 0xffffu) + pre2;
    int p3 = (int)(oCD >> 16)     + pre3;
#pragma unroll
    for (int k = 0; k < 4; ++k) {
        if (isfinite(v0[k])) s[0][p0++] = v0[k];
        if (isfinite(v1[k])) s[1][p1++] = v1[k];
        if (isfinite(v2[k])) s[2][p2++] = v2[k];
        if (isfinite(v3[k])) s[3][p3++] = v3[k];
    }
    __syncthreads();

    // Epilogue: broadcast w/b (L1-hot), affine + zero tail, streaming stores.
    const float4 wv = __ldg(&w4[t]);
    const float4 bv = __ldg(&b4[t]);
    const int base = t << 2;

    const float4 c0 = reinterpret_cast<const float4*>(s[0])[t];
    const float4 c1 = reinterpret_cast<const float4*>(s[1])[t];
    const float4 c2 = reinterpret_cast<const float4*>(s[2])[t];
    const float4 c3 = reinterpret_cast<const float4*>(s[3])[t];

    float4 o;
    o.x = (base + 0 < tot0) ? fmaf(c0.x, wv.x, bv.x) : 0.0f;
    o.y = (base + 1 < tot0) ? fmaf(c0.y, wv.y, bv.y) : 0.0f;
    o.z = (base + 2 < tot0) ? fmaf(c0.z, wv.z, bv.z) : 0.0f;
    o.w = (base + 3 < tot0) ? fmaf(c0.w, wv.w, bv.w) : 0.0f;
    __stcs(&out4[(r0 + 0) * V + t], o);

    o.x = (base + 0 < tot1) ? fmaf(c1.x, wv.x, bv.x) : 0.0f;
    o.y = (base + 1 < tot1) ? fmaf(c1.y, wv.y, bv.y) : 0.0f;
    o.z = (base + 2 < tot1) ? fmaf(c1.z, wv.z, bv.z) : 0.0f;
    o.w = (base + 3 < tot1) ? fmaf(c1.w, wv.w, bv.w) : 0.0f;
    __stcs(&out4[(r0 + 1) * V + t], o);

    o.x = (base + 0 < tot2) ? fmaf(c2.x, wv.x, bv.x) : 0.0f;
    o.y = (base + 1 < tot2) ? fmaf(c2.y, wv.y, bv.y) : 0.0f;
    o.z = (base + 2 < tot2) ? fmaf(c2.z, wv.z, bv.z) : 0.0f;
    o.w = (base + 3 < tot2) ? fmaf(c2.w, wv.w, bv.w) : 0.0f;
    __stcs(&out4[(r0 + 2) * V + t], o);

    o.x = (base + 0 < tot3) ? fmaf(c3.x, wv.x, bv.x) : 0.0f;
    o.y = (base + 1 < tot3) ? fmaf(c3.y, wv.y, bv.y) : 0.0f;
    o.z = (base + 2 < tot3) ? fmaf(c3.z, wv.z, bv.z) : 0.0f;
    o.w = (base + 3 < tot3) ? fmaf(c3.w, wv.w, bv.w) : 0.0f;
    __stcs(&out4[(r0 + 3) * V + t], o);
}

extern "C" void kernel_launch(void* const* d_in, const int* in_sizes, int n_in,
                              void* d_out, int out_size)
{
    const float* X = (const float*)d_in[0];
    const float* w = (const float*)d_in[1];
    const float* b = (const float*)d_in[2];
    float* out = (float*)d_out;

    const int batch = in_sizes[0] / SIZE;   // 131072 (multiple of 4)
    nan_dense_kernel<<<batch / ROWS, THREADS>>>(
        reinterpret_cast<const float4*>(X),
        reinterpret_cast<const float4*>(w),
        reinterpret_cast<const float4*>(b),
        reinterpret_cast<float4*>(out));
}

// round 8
// speedup vs baseline: 1.3536x; 1.0619x over previous
#include <cuda_runtime.h>
#include <math.h>

// 256 threads/CTA, 4 rows per CTA. All 4 rows staged global->shared via
// cp.async.cg (register-free, L1-allocate-free), one commit group per row;
// rows processed one at a time (wait_group 3-r overlaps row r compute with
// rows r+1.. DRAM latency). Only 4 row floats live at a time -> lean regs
// -> 6 CTAs/SM with MLP decoupled from registers. Each thread reads back
// only its own cp.async bytes, so no sync between wait and readback.
// Ballot-based stable compaction; w/b register-resident (loaded once);
// streaming __stcs stores.

#define SIZE 1024
#define THREADS 256
#define ROWS 4

__global__ __launch_bounds__(THREADS, 6)
void nan_dense_kernel(const float* __restrict__ X,
                      const float4* __restrict__ w4,
                      const float4* __restrict__ b4,
                      float4* __restrict__ out4)
{
    __shared__ float raw[ROWS * SIZE];      // 16 KB staging
    __shared__ float cmp[SIZE];             // 4 KB compaction buffer
    __shared__ int wtot[8];

    const int t    = threadIdx.x;
    const int lane = t & 31;
    const int wid  = t >> 5;
    const int V    = SIZE / 4;

    const long long r0 = (long long)blockIdx.x * ROWS;
    const float* gsrc = X + r0 * SIZE + (t << 2);

    const unsigned raw_sa = (unsigned)__cvta_generic_to_shared(raw) + (t << 4);

    // Stage all four rows; one commit group per row (FIFO completion).
#pragma unroll
    for (int r = 0; r < ROWS; ++r) {
        asm volatile(
            "cp.async.cg.shared.global [%0], [%1], 16;\n\t"
            "cp.async.commit_group;\n"
            :: "r"(raw_sa + r * (SIZE * 4)), "l"(gsrc + r * SIZE)
            : "memory");
    }

    const float4 wv = __ldg(&w4[t]);
    const float4 bv = __ldg(&b4[t]);
    const unsigned lt = (1u << lane) - 1u;
    const int base = t << 2;

#pragma unroll
    for (int r = 0; r < ROWS; ++r) {
        // Wait until this row's group has landed (groups retire in order).
        switch (r) {
            case 0: asm volatile("cp.async.wait_group 3;" ::: "memory"); break;
            case 1: asm volatile("cp.async.wait_group 2;" ::: "memory"); break;
            case 2: asm volatile("cp.async.wait_group 1;" ::: "memory"); break;
            default: asm volatile("cp.async.wait_group 0;" ::: "memory"); break;
        }

        // Read back own 16 bytes (written by this thread's own cp.async).
        const float4 cur = reinterpret_cast<const float4*>(raw)[r * V + t];
        float v[4] = {cur.x, cur.y, cur.z, cur.w};

        int pre = 0, wt = 0;
#pragma unroll
        for (int k = 0; k < 4; ++k) {
            const unsigned m = __ballot_sync(0xffffffffu, isfinite(v[k]));
            pre += __popc(m & lt);
            wt  += __popc(m);
        }
        if (lane == 0) wtot[wid] = wt;
        __syncthreads();   // wtot visible; also orders prev row's cmp reads

        int off = 0, total = 0;
#pragma unroll
        for (int i = 0; i < 8; ++i) {
            const int ti = wtot[i];
            total += ti;
            if (i < wid) off += ti;
        }

        int pos = off + pre;
#pragma unroll
        for (int k = 0; k < 4; ++k) {
            if (isfinite(v[k])) cmp[pos++] = v[k];
        }
        __syncthreads();   // scatter complete

        const float4 sv = reinterpret_cast<const float4*>(cmp)[t];
        float4 o;
        o.x = (base + 0 < total) ? fmaf(sv.x, wv.x, bv.x) : 0.0f;
        o.y = (base + 1 < total) ? fmaf(sv.y, wv.y, bv.y) : 0.0f;
        o.z = (base + 2 < total) ? fmaf(sv.z, wv.z, bv.z) : 0.0f;
        o.w = (base + 3 < total) ? fmaf(sv.w, wv.w, bv.w) : 0.0f;

        __stcs(&out4[(r0 + r) * V + t], o);
    }
}

extern "C" void kernel_launch(void* const* d_in, const int* in_sizes, int n_in,
                              void* d_out, int out_size)
{
    const float* X = (const float*)d_in[0];
    const float* w = (const float*)d_in[1];
    const float* b = (const float*)d_in[2];
    float* out = (float*)d_out;

    const int batch = in_sizes[0] / SIZE;   // 131072 (multiple of 4)
    nan_dense_kernel<<<batch / ROWS, THREADS>>>(
        X,
        reinterpret_cast<const float4*>(w),
        reinterpret_cast<const float4*>(b),
        reinterpret_cast<float4*>(out));
}